// round 10
// baseline (speedup 1.0000x reference)
#include <cuda_runtime.h>
#include <cuda_fp16.h>
#include <math.h>

constexpr int FIN     = 8;
constexpr int E_TOTAL = 262144;
constexpr int NBASIS  = 10;
constexpr int HID     = 64;
constexpr int WN      = 384;
constexpr int NNODES  = 32768;

// Radial table: 16 live difference-functions of r on [0,3], fp16, 32B rows.
// Row p: h[0..7] = c0[u] = g_{u,2}-g_{u,1}; h[8..15] = c1[u] = g_{u,0}-g_{u,2}.
// curl0 = x.c0, curl1 = x.c1, curl2 = -(curl0+curl1).
constexpr int NB = 2048;
__device__ __half g_tab_h[(NB + 1) * 16];
__device__ float4 g_pos4[NNODES];     // padded positions
__device__ uint4  g_nf16[NNODES];     // node features as half8
__device__ int g_flag  = 0;
__device__ int g_pdone = 0;
__device__ int g_cdone = 0;

__device__ __forceinline__ unsigned h2_bits(__half2 h) {
    union { __half2 h; unsigned u; } c; c.h = h; return c.u;
}
__device__ __forceinline__ float2 h2f(unsigned u) {
    union { unsigned u; __half2 h; } c; c.u = u;
    return __half22float2(c.h);
}
__device__ __forceinline__ float dot8(uint4 t, float2 X0, float2 X1,
                                      float2 X2, float2 X3) {
    float2 t0 = h2f(t.x), t1 = h2f(t.y), t2 = h2f(t.z), t3 = h2f(t.w);
    return X0.x*t0.x + X0.y*t0.y + X1.x*t1.x + X1.y*t1.y
         + X2.x*t2.x + X2.y*t2.y + X3.x*t3.x + X3.y*t3.y;
}

// Producer role partition (all these blocks are also edge consumers).
constexpr int TDIM     = 256;
constexpr int GRID     = E_TOTAL / TDIM;       // 1024
constexpr int T_BLOCKS = 33;                   // 8448 lane-tasks >= 2049*4
constexpr int Z_END    = T_BLOCKS + 96;        // 96*256 float4 = out
constexpr int P4_END   = Z_END + 128;          // 32768 nodes
constexpr int NF_END   = P4_END + 128;         // 32768 nodes
constexpr int P_TOTAL  = NF_END;               // 385

__global__ void __launch_bounds__(TDIM, 6)
fused_kernel(const float* __restrict__ nf,
             const float* __restrict__ pos,
             const int*   __restrict__ esrc,
             const int*   __restrict__ edst,
             const float* __restrict__ W1,
             const float* __restrict__ W2,
             float*       __restrict__ out) {
    const int bid = blockIdx.x;
    const int tid = threadIdx.x;

    // ---- edge index prefetch (coalesced, independent of producers) ----
    const int e = bid * TDIM + tid;
    const int s = __ldg(esrc + e);
    const int d = __ldg(edst + e);

    // ===================== PRODUCER DUTY (blocks 0..384) ====================
    if (bid < P_TOTAL) {
        if (bid < T_BLOCKS) {
            __shared__ float sW1[NBASIS * HID];   // 640
            __shared__ float sW2d[HID * 16];      // pre-differenced W2 cols

            for (int i = tid; i < NBASIS * HID; i += TDIM) sW1[i] = W1[i];
            for (int i = tid; i < HID * 16; i += TDIM) {
                int k = i >> 4, c = i & 15, u = c & 7;
                const float* w = W2 + k * WN + u * 32;
                sW2d[i] = (c < 8) ? (w[2] - w[1]) : (w[0] - w[2]);
            }
            __syncthreads();

            int g  = bid * TDIM + tid;
            int p  = g >> 2;                      // table point
            int k0 = (g & 3) * 16;                // this lane's k-chunk

            float r = 3.0f * (float)min(p, NB) / (float)NB;

            float emb[NBASIS];
            const float inv_step = 11.0f / 3.0f;
            const float cA = 1.14136f * __expf(2.0f) * sqrtf(10.0f);
            #pragma unroll
            for (int j = 0; j < NBASIS; j++) {
                float v  = 3.0f * (float)(j + 1) / 11.0f;
                float dd = (r - v) * inv_step;
                float ee = 0.0f;
                if (fabsf(dd) < 1.0f) {
                    float y = fmaxf(1.0f - dd * dd, 1e-7f);
                    ee = cA * __expf(-1.0f / y);
                }
                emb[j] = ee;
            }

            float acc[16];
            #pragma unroll
            for (int c = 0; c < 16; c++) acc[c] = 0.0f;

            #pragma unroll
            for (int kk = 0; kk < 16; kk++) {
                float sv = 0.0f;
                #pragma unroll
                for (int j = 0; j < NBASIS; j++)
                    sv = fmaf(emb[j], sW1[j * HID + k0 + kk], sv);
                sv *= 0.31622776601683794f;                    // 1/sqrt(10)
                float hk = __fdividef(sv, 1.0f + __expf(-sv)); // silu
                #pragma unroll
                for (int c = 0; c < 16; c++)
                    acc[c] = fmaf(hk, sW2d[(k0 + kk) * 16 + c], acc[c]);
            }

            #pragma unroll
            for (int o = 1; o <= 2; o <<= 1) {
                #pragma unroll
                for (int c = 0; c < 16; c++)
                    acc[c] += __shfl_xor_sync(0xffffffffu, acc[c], o);
            }

            if ((g & 3) == 0 && p <= NB) {
                float t    = 10.0f * (1.0f - r * (1.0f / 3.0f));
                float wcut = (t > 0.0f) ? __expf(-1.0f / t) : 0.0f;
                float sc   = wcut * 0.04419417382415922f;  // (1/8)*(1/sqrt8)
                __half2* row = (__half2*)(g_tab_h + (size_t)p * 16);
                #pragma unroll
                for (int c = 0; c < 8; c++)
                    row[c] = __floats2half2_rn(acc[2*c] * sc, acc[2*c+1] * sc);
            }
        } else if (bid < Z_END) {
            int i = (bid - T_BLOCKS) * TDIM + tid;       // zero poisoned out
            ((float4*)out)[i] = make_float4(0.f, 0.f, 0.f, 0.f);
        } else if (bid < P4_END) {
            int n = (bid - Z_END) * TDIM + tid;
            g_pos4[n] = make_float4(__ldg(pos + 3*n), __ldg(pos + 3*n + 1),
                                    __ldg(pos + 3*n + 2), 0.f);
        } else {
            int n = (bid - P4_END) * TDIM + tid;
            const float4* xp = (const float4*)(nf + (size_t)n * FIN);
            float4 a = __ldg(xp), b = __ldg(xp + 1);
            uint4 h;
            h.x = h2_bits(__floats2half2_rn(a.x, a.y));
            h.y = h2_bits(__floats2half2_rn(a.z, a.w));
            h.z = h2_bits(__floats2half2_rn(b.x, b.y));
            h.w = h2_bits(__floats2half2_rn(b.z, b.w));
            g_nf16[n] = h;
        }
        __threadfence();
        __syncthreads();
        if (tid == 0) {
            if (atomicAdd(&g_pdone, 1) == P_TOTAL - 1)
                atomicExch(&g_flag, 1);
        }
    }

    // ---- wait for producers (wave-1 bids 0..384 guarantee progress) ----
    if (tid == 0) {
        volatile int* f = &g_flag;
        while (*f == 0) __nanosleep(64);
    }
    __syncthreads();
    __threadfence();

    // ===================== EDGE COMPUTE (1 edge/thread) =====================
    float4 ps = __ldg(g_pos4 + s);
    float4 pd = __ldg(g_pos4 + d);
    uint4  xh = __ldg(g_nf16 + s);

    float dx = ps.x - pd.x, dy = ps.y - pd.y, dz = ps.z - pd.z;
    float r  = sqrtf(fmaf(dx, dx, fmaf(dy, dy, fmaf(dz, dz, 1e-18f))));

    if (r < 3.0f) {                           // w_cut == 0 otherwise
        float ff = r * ((float)NB / 3.0f);
        int   i  = (int)ff;
        float fr = ff - (float)i;

        const uint4* tp = (const uint4*)(g_tab_h + (size_t)i * 16);
        uint4 ta = __ldg(tp + 0);   // c0, row i
        uint4 tb = __ldg(tp + 1);   // c1, row i
        uint4 tc = __ldg(tp + 2);   // c0, row i+1
        uint4 td = __ldg(tp + 3);   // c1, row i+1

        float2 X0 = h2f(xh.x), X1 = h2f(xh.y), X2 = h2f(xh.z), X3 = h2f(xh.w);
        float c0a = dot8(ta, X0, X1, X2, X3);
        float c1a = dot8(tb, X0, X1, X2, X3);
        float c0b = dot8(tc, X0, X1, X2, X3);
        float c1b = dot8(td, X0, X1, X2, X3);

        float curl0 = fmaf(fr, c0b - c0a, c0a);
        float curl1 = fmaf(fr, c1b - c1a, c1a);
        float curl2 = -(curl0 + curl1);

        // 2 atomics: out+3d is 8B-aligned iff d even; else out+3d+1 is.
        if (d & 1) {
            atomicAdd(out + 3*d, curl0);
            atomicAdd((float2*)(out + 3*d + 1), make_float2(curl1, curl2));
        } else {
            atomicAdd((float2*)(out + 3*d), make_float2(curl0, curl1));
            atomicAdd(out + 3*d + 2, curl2);
        }
    }

    // ---- last block resets state so the next graph replay starts clean ----
    __syncthreads();
    if (tid == 0) {
        if (atomicAdd(&g_cdone, 1) == GRID - 1) {
            g_pdone = 0;
            g_cdone = 0;
            __threadfence();
            atomicExch(&g_flag, 0);
        }
    }
}

// ---------------------------------------------------------------------------
extern "C" void kernel_launch(void* const* d_in, const int* in_sizes, int n_in,
                              void* d_out, int out_size) {
    const float* nf   = (const float*)d_in[0];
    const float* pos  = (const float*)d_in[1];
    const int*   esrc = (const int*)  d_in[2];
    const int*   edst = (const int*)  d_in[3];
    const float* W1   = (const float*)d_in[4];
    const float* W2   = (const float*)d_in[5];
    float* out = (float*)d_out;

    fused_kernel<<<GRID, TDIM>>>(nf, pos, esrc, edst, W1, W2, out);
}

// round 11
// speedup vs baseline: 1.2717x; 1.2717x over previous
#include <cuda_runtime.h>
#include <cuda_fp16.h>
#include <math.h>

constexpr int FIN     = 8;
constexpr int E_TOTAL = 262144;
constexpr int NBASIS  = 10;
constexpr int HID     = 64;
constexpr int WN      = 384;
constexpr int NNODES  = 32768;

// Radial table: 16 live difference-functions of r on [0,3], fp16, 32B rows.
// Row p: h[0..7] = c0[u] = g_{u,2}-g_{u,1}; h[8..15] = c1[u] = g_{u,0}-g_{u,2}.
// curl0 = x.c0, curl1 = x.c1, curl2 = -(curl0+curl1).
constexpr int NB = 2048;
__device__ __half g_tab_h[(NB + 1) * 16];
__device__ float4 g_pos4[NNODES];     // padded positions
__device__ uint4  g_nf16[NNODES];     // node features as half8

__device__ __forceinline__ unsigned h2_bits(__half2 h) {
    union { __half2 h; unsigned u; } c; c.h = h; return c.u;
}
__device__ __forceinline__ float2 h2f(unsigned u) {
    union { unsigned u; __half2 h; } c; c.u = u;
    return __half22float2(c.h);
}

// ---------------------------------------------------------------------------
// Setup kernel roles: [0,T) table (4 lanes/point, k-chunks of 16),
// [T,Z) zero poisoned output, [Z,P) pos->float4, [P,...) nf->half8.
// ---------------------------------------------------------------------------
constexpr int STD      = 256;
constexpr int T_BLOCKS = 33;             // 8448 lane-tasks >= 2049*4
constexpr int Z_END    = T_BLOCKS + 96;  // 96*256 float4 = 98304 floats = out
constexpr int P4_END   = Z_END + 128;    // 32768 nodes
constexpr int NF_END   = P4_END + 128;   // 32768 nodes
constexpr int S_GRID   = NF_END;         // 385

__global__ void __launch_bounds__(STD)
setup_kernel(const float* __restrict__ nf,
             const float* __restrict__ pos,
             const float* __restrict__ W1,
             const float* __restrict__ W2,
             float* __restrict__ out) {
    const int bid = blockIdx.x;
    const int tid = threadIdx.x;

    if (bid < T_BLOCKS) {
        __shared__ float sW1[NBASIS * HID];   // 640
        __shared__ float sW2d[HID * 16];      // pre-differenced live W2 cols

        for (int i = tid; i < NBASIS * HID; i += STD) sW1[i] = W1[i];
        for (int i = tid; i < HID * 16; i += STD) {
            int k = i >> 4, c = i & 15, u = c & 7;
            const float* w = W2 + k * WN + u * 32;
            sW2d[i] = (c < 8) ? (w[2] - w[1]) : (w[0] - w[2]);
        }
        __syncthreads();

        int g  = bid * STD + tid;
        int p  = g >> 2;                      // table point
        int k0 = (g & 3) * 16;                // this lane's k-chunk

        float r = 3.0f * (float)min(p, NB) / (float)NB;

        float emb[NBASIS];
        const float inv_step = 11.0f / 3.0f;
        const float cA = 1.14136f * __expf(2.0f) * sqrtf(10.0f);
        #pragma unroll
        for (int j = 0; j < NBASIS; j++) {
            float v  = 3.0f * (float)(j + 1) / 11.0f;
            float dd = (r - v) * inv_step;
            float e  = 0.0f;
            if (fabsf(dd) < 1.0f) {
                float y = fmaxf(1.0f - dd * dd, 1e-7f);
                e = cA * __expf(-1.0f / y);
            }
            emb[j] = e;
        }

        float acc[16];
        #pragma unroll
        for (int c = 0; c < 16; c++) acc[c] = 0.0f;

        #pragma unroll
        for (int kk = 0; kk < 16; kk++) {
            float s = 0.0f;
            #pragma unroll
            for (int j = 0; j < NBASIS; j++)
                s = fmaf(emb[j], sW1[j * HID + k0 + kk], s);
            s *= 0.31622776601683794f;                    // 1/sqrt(10)
            float hk = __fdividef(s, 1.0f + __expf(-s));  // silu
            #pragma unroll
            for (int c = 0; c < 16; c++)
                acc[c] = fmaf(hk, sW2d[(k0 + kk) * 16 + c], acc[c]);
        }

        // Combine the 4 k-chunk lanes (g, g^1, g^2) of this table point.
        #pragma unroll
        for (int o = 1; o <= 2; o <<= 1) {
            #pragma unroll
            for (int c = 0; c < 16; c++)
                acc[c] += __shfl_xor_sync(0xffffffffu, acc[c], o);
        }

        if ((g & 3) == 0 && p <= NB) {
            float t    = 10.0f * (1.0f - r * (1.0f / 3.0f));
            float wcut = (t > 0.0f) ? __expf(-1.0f / t) : 0.0f;
            float sc   = wcut * 0.04419417382415922f;   // (1/8)*(1/sqrt8)
            __half2* row = (__half2*)(g_tab_h + (size_t)p * 16);
            #pragma unroll
            for (int c = 0; c < 8; c++)
                row[c] = __floats2half2_rn(acc[2*c] * sc, acc[2*c+1] * sc);
        }
    } else if (bid < Z_END) {
        int i = (bid - T_BLOCKS) * STD + tid;         // zero poisoned output
        ((float4*)out)[i] = make_float4(0.f, 0.f, 0.f, 0.f);
    } else if (bid < P4_END) {
        int n = (bid - Z_END) * STD + tid;
        g_pos4[n] = make_float4(__ldg(pos + 3*n), __ldg(pos + 3*n + 1),
                                __ldg(pos + 3*n + 2), 0.f);
    } else {
        int n = (bid - P4_END) * STD + tid;
        const float4* xp = (const float4*)(nf + (size_t)n * FIN);
        float4 a = __ldg(xp), b = __ldg(xp + 1);
        uint4 h;
        h.x = h2_bits(__floats2half2_rn(a.x, a.y));
        h.y = h2_bits(__floats2half2_rn(a.z, a.w));
        h.z = h2_bits(__floats2half2_rn(b.x, b.y));
        h.w = h2_bits(__floats2half2_rn(b.z, b.w));
        g_nf16[n] = h;
    }
}

// ---------------------------------------------------------------------------
// Edge kernel (proven 9.5us shape): 1 edge/thread; fp16 table lerp;
// parity-split vector atomics (2 REDs instead of 3).
// ---------------------------------------------------------------------------
__device__ __forceinline__ float dot8(uint4 t, float2 X0, float2 X1,
                                      float2 X2, float2 X3) {
    float2 t0 = h2f(t.x), t1 = h2f(t.y), t2 = h2f(t.z), t3 = h2f(t.w);
    return X0.x*t0.x + X0.y*t0.y + X1.x*t1.x + X1.y*t1.y
         + X2.x*t2.x + X2.y*t2.y + X3.x*t3.x + X3.y*t3.y;
}

__global__ void __launch_bounds__(256)
edge_kernel(const int* __restrict__ esrc,
            const int* __restrict__ edst,
            float*     __restrict__ out) {
    int e = blockIdx.x * 256 + threadIdx.x;

    int s = __ldg(esrc + e);
    int d = __ldg(edst + e);

    float4 ps = __ldg(g_pos4 + s);
    float4 pd = __ldg(g_pos4 + d);
    uint4  xh = __ldg(g_nf16 + s);

    float dx = ps.x - pd.x, dy = ps.y - pd.y, dz = ps.z - pd.z;
    float r  = sqrtf(fmaf(dx, dx, fmaf(dy, dy, fmaf(dz, dz, 1e-18f))));

    if (r >= 3.0f) return;                    // w_cut == 0

    float ff = r * ((float)NB / 3.0f);
    int   i  = (int)ff;
    float fr = ff - (float)i;

    const uint4* tp = (const uint4*)(g_tab_h + (size_t)i * 16);
    uint4 ta = __ldg(tp + 0);   // c0, row i
    uint4 tb = __ldg(tp + 1);   // c1, row i
    uint4 tc = __ldg(tp + 2);   // c0, row i+1
    uint4 td = __ldg(tp + 3);   // c1, row i+1

    float2 X0 = h2f(xh.x), X1 = h2f(xh.y), X2 = h2f(xh.z), X3 = h2f(xh.w);
    float c0a = dot8(ta, X0, X1, X2, X3);
    float c1a = dot8(tb, X0, X1, X2, X3);
    float c0b = dot8(tc, X0, X1, X2, X3);
    float c1b = dot8(td, X0, X1, X2, X3);

    float curl0 = fmaf(fr, c0b - c0a, c0a);
    float curl1 = fmaf(fr, c1b - c1a, c1a);
    float curl2 = -(curl0 + curl1);

    // out+3d is 8B-aligned iff d even; else out+3d+1 is.
    if (d & 1) {
        atomicAdd(out + 3*d, curl0);
        atomicAdd((float2*)(out + 3*d + 1), make_float2(curl1, curl2));
    } else {
        atomicAdd((float2*)(out + 3*d), make_float2(curl0, curl1));
        atomicAdd(out + 3*d + 2, curl2);
    }
}

// ---------------------------------------------------------------------------
extern "C" void kernel_launch(void* const* d_in, const int* in_sizes, int n_in,
                              void* d_out, int out_size) {
    const float* nf   = (const float*)d_in[0];
    const float* pos  = (const float*)d_in[1];
    const int*   esrc = (const int*)  d_in[2];
    const int*   edst = (const int*)  d_in[3];
    const float* W1   = (const float*)d_in[4];
    const float* W2   = (const float*)d_in[5];
    float* out = (float*)d_out;

    setup_kernel<<<S_GRID, STD>>>(nf, pos, W1, W2, out);
    edge_kernel<<<E_TOTAL / 256, 256>>>(esrc, edst, out);
}

// round 12
// speedup vs baseline: 1.3384x; 1.0525x over previous
#include <cuda_runtime.h>
#include <cuda_fp16.h>
#include <math.h>

constexpr int FIN     = 8;
constexpr int E_TOTAL = 262144;
constexpr int NBASIS  = 10;
constexpr int HID     = 64;
constexpr int WN      = 384;
constexpr int NNODES  = 32768;

// Radial table: 16 live difference-functions of r on [0,3], fp16, 32B rows.
// Row p: h[0..7] = c0[u] = g_{u,2}-g_{u,1}; h[8..15] = c1[u] = g_{u,0}-g_{u,2}.
// curl0 = x.c0, curl1 = x.c1, curl2 = -(curl0+curl1).
constexpr int NB = 2048;
__device__ __half g_tab_h[(NB + 1) * 16];
__device__ float4 g_pos4[NNODES];     // padded positions
__device__ uint4  g_nf16[NNODES];     // node features as half8

__device__ __forceinline__ unsigned h2_bits(__half2 h) {
    union { __half2 h; unsigned u; } c; c.h = h; return c.u;
}
__device__ __forceinline__ float2 h2f(unsigned u) {
    union { unsigned u; __half2 h; } c; c.u = u;
    return __half22float2(c.h);
}

// ---------------------------------------------------------------------------
// Setup kernel roles: [0,T) table (4 lanes/point, k-chunks of 16),
// [T,Z) zero poisoned output, [Z,P) pos->float4, [P,...) nf->half8.
// ---------------------------------------------------------------------------
constexpr int STD      = 256;
constexpr int T_BLOCKS = 33;             // 8448 lane-tasks >= 2049*4
constexpr int Z_END    = T_BLOCKS + 96;  // 96*256 float4 = 98304 floats = out
constexpr int P4_END   = Z_END + 128;    // 32768 nodes
constexpr int NF_END   = P4_END + 128;   // 32768 nodes
constexpr int S_GRID   = NF_END;         // 385

__global__ void __launch_bounds__(STD)
setup_kernel(const float* __restrict__ nf,
             const float* __restrict__ pos,
             const float* __restrict__ W1,
             const float* __restrict__ W2,
             float* __restrict__ out) {
    // Allow the dependent edge kernel to start launching immediately; its
    // cudaGridDependencySynchronize() still waits for our full completion.
    cudaTriggerProgrammaticLaunchCompletion();

    const int bid = blockIdx.x;
    const int tid = threadIdx.x;

    if (bid < T_BLOCKS) {
        __shared__ float sW1[NBASIS * HID];   // 640
        __shared__ float sW2d[HID * 16];      // pre-differenced live W2 cols

        for (int i = tid; i < NBASIS * HID; i += STD) sW1[i] = W1[i];
        for (int i = tid; i < HID * 16; i += STD) {
            int k = i >> 4, c = i & 15, u = c & 7;
            const float* w = W2 + k * WN + u * 32;
            sW2d[i] = (c < 8) ? (w[2] - w[1]) : (w[0] - w[2]);
        }
        __syncthreads();

        int g  = bid * STD + tid;
        int p  = g >> 2;                      // table point
        int k0 = (g & 3) * 16;                // this lane's k-chunk

        float r = 3.0f * (float)min(p, NB) / (float)NB;

        float emb[NBASIS];
        const float inv_step = 11.0f / 3.0f;
        const float cA = 1.14136f * __expf(2.0f) * sqrtf(10.0f);
        #pragma unroll
        for (int j = 0; j < NBASIS; j++) {
            float v  = 3.0f * (float)(j + 1) / 11.0f;
            float dd = (r - v) * inv_step;
            float e  = 0.0f;
            if (fabsf(dd) < 1.0f) {
                float y = fmaxf(1.0f - dd * dd, 1e-7f);
                e = cA * __expf(-1.0f / y);
            }
            emb[j] = e;
        }

        float acc[16];
        #pragma unroll
        for (int c = 0; c < 16; c++) acc[c] = 0.0f;

        #pragma unroll
        for (int kk = 0; kk < 16; kk++) {
            float s = 0.0f;
            #pragma unroll
            for (int j = 0; j < NBASIS; j++)
                s = fmaf(emb[j], sW1[j * HID + k0 + kk], s);
            s *= 0.31622776601683794f;                    // 1/sqrt(10)
            float hk = __fdividef(s, 1.0f + __expf(-s));  // silu
            #pragma unroll
            for (int c = 0; c < 16; c++)
                acc[c] = fmaf(hk, sW2d[(k0 + kk) * 16 + c], acc[c]);
        }

        // Combine the 4 k-chunk lanes (g, g^1, g^2) of this table point.
        #pragma unroll
        for (int o = 1; o <= 2; o <<= 1) {
            #pragma unroll
            for (int c = 0; c < 16; c++)
                acc[c] += __shfl_xor_sync(0xffffffffu, acc[c], o);
        }

        if ((g & 3) == 0 && p <= NB) {
            float t    = 10.0f * (1.0f - r * (1.0f / 3.0f));
            float wcut = (t > 0.0f) ? __expf(-1.0f / t) : 0.0f;
            float sc   = wcut * 0.04419417382415922f;   // (1/8)*(1/sqrt8)
            __half2* row = (__half2*)(g_tab_h + (size_t)p * 16);
            #pragma unroll
            for (int c = 0; c < 8; c++)
                row[c] = __floats2half2_rn(acc[2*c] * sc, acc[2*c+1] * sc);
        }
    } else if (bid < Z_END) {
        int i = (bid - T_BLOCKS) * STD + tid;         // zero poisoned output
        ((float4*)out)[i] = make_float4(0.f, 0.f, 0.f, 0.f);
    } else if (bid < P4_END) {
        int n = (bid - Z_END) * STD + tid;
        g_pos4[n] = make_float4(__ldg(pos + 3*n), __ldg(pos + 3*n + 1),
                                __ldg(pos + 3*n + 2), 0.f);
    } else {
        int n = (bid - P4_END) * STD + tid;
        const float4* xp = (const float4*)(nf + (size_t)n * FIN);
        float4 a = __ldg(xp), b = __ldg(xp + 1);
        uint4 h;
        h.x = h2_bits(__floats2half2_rn(a.x, a.y));
        h.y = h2_bits(__floats2half2_rn(a.z, a.w));
        h.z = h2_bits(__floats2half2_rn(b.x, b.y));
        h.w = h2_bits(__floats2half2_rn(b.z, b.w));
        g_nf16[n] = h;
    }
}

// ---------------------------------------------------------------------------
// Edge kernel (PDL secondary): coalesced idx preamble, HW dependency wait,
// then the proven 9.5us body (fp16 table lerp, parity-split vector atomics).
// ---------------------------------------------------------------------------
__device__ __forceinline__ float dot8(uint4 t, float2 X0, float2 X1,
                                      float2 X2, float2 X3) {
    float2 t0 = h2f(t.x), t1 = h2f(t.y), t2 = h2f(t.z), t3 = h2f(t.w);
    return X0.x*t0.x + X0.y*t0.y + X1.x*t1.x + X1.y*t1.y
         + X2.x*t2.x + X2.y*t2.y + X3.x*t3.x + X3.y*t3.y;
}

__global__ void __launch_bounds__(256)
edge_kernel(const int* __restrict__ esrc,
            const int* __restrict__ edst,
            float*     __restrict__ out) {
    int e = blockIdx.x * 256 + threadIdx.x;

    // Preamble: independent of setup outputs — overlaps with setup execution.
    int s = __ldg(esrc + e);
    int d = __ldg(edst + e);

    // HW wait until setup_kernel has fully completed (memory visible).
    cudaGridDependencySynchronize();

    float4 ps = __ldg(g_pos4 + s);
    float4 pd = __ldg(g_pos4 + d);
    uint4  xh = __ldg(g_nf16 + s);

    float dx = ps.x - pd.x, dy = ps.y - pd.y, dz = ps.z - pd.z;
    float r  = sqrtf(fmaf(dx, dx, fmaf(dy, dy, fmaf(dz, dz, 1e-18f))));

    if (r >= 3.0f) return;                    // w_cut == 0

    float ff = r * ((float)NB / 3.0f);
    int   i  = (int)ff;
    float fr = ff - (float)i;

    const uint4* tp = (const uint4*)(g_tab_h + (size_t)i * 16);
    uint4 ta = __ldg(tp + 0);   // c0, row i
    uint4 tb = __ldg(tp + 1);   // c1, row i
    uint4 tc = __ldg(tp + 2);   // c0, row i+1
    uint4 td = __ldg(tp + 3);   // c1, row i+1

    float2 X0 = h2f(xh.x), X1 = h2f(xh.y), X2 = h2f(xh.z), X3 = h2f(xh.w);
    float c0a = dot8(ta, X0, X1, X2, X3);
    float c1a = dot8(tb, X0, X1, X2, X3);
    float c0b = dot8(tc, X0, X1, X2, X3);
    float c1b = dot8(td, X0, X1, X2, X3);

    float curl0 = fmaf(fr, c0b - c0a, c0a);
    float curl1 = fmaf(fr, c1b - c1a, c1a);
    float curl2 = -(curl0 + curl1);

    // out+3d is 8B-aligned iff d even; else out+3d+1 is.
    if (d & 1) {
        atomicAdd(out + 3*d, curl0);
        atomicAdd((float2*)(out + 3*d + 1), make_float2(curl1, curl2));
    } else {
        atomicAdd((float2*)(out + 3*d), make_float2(curl0, curl1));
        atomicAdd(out + 3*d + 2, curl2);
    }
}

// ---------------------------------------------------------------------------
extern "C" void kernel_launch(void* const* d_in, const int* in_sizes, int n_in,
                              void* d_out, int out_size) {
    const float* nf   = (const float*)d_in[0];
    const float* pos  = (const float*)d_in[1];
    const int*   esrc = (const int*)  d_in[2];
    const int*   edst = (const int*)  d_in[3];
    const float* W1   = (const float*)d_in[4];
    const float* W2   = (const float*)d_in[5];
    float* out = (float*)d_out;

    setup_kernel<<<S_GRID, STD>>>(nf, pos, W1, W2, out);

    // Launch the edge kernel as a PDL secondary: it may begin before
    // setup_kernel finishes; cudaGridDependencySynchronize() inside
    // enforces the data dependency.
    cudaLaunchConfig_t cfg = {};
    cfg.gridDim  = dim3(E_TOTAL / 256);
    cfg.blockDim = dim3(256);
    cfg.stream   = 0;
    cudaLaunchAttribute attrs[1];
    attrs[0].id = cudaLaunchAttributeProgrammaticStreamSerialization;
    attrs[0].val.programmaticStreamSerializationAllowed = 1;
    cfg.attrs    = attrs;
    cfg.numAttrs = 1;
    cudaLaunchKernelEx(&cfg, edge_kernel, esrc, edst, out);
}